// round 12
// baseline (speedup 1.0000x reference)
#include <cuda_runtime.h>
#include <cstdint>
#include <math.h>

#define DIMS   128
#define BINSZ  500
#define TILE_R 64
#define TILE_C 64
#define SPLITS 2
#define CPS    250      // cols per split
#define MAXPTS 65536

// scratch (allocation-free rule: __device__ globals)
__device__ int   g_binid[MAXPTS];
__device__ float g_na[MAXPTS];
__device__ int   g_split[MAXPTS];
__device__ float g_sorted[(size_t)MAXPTS * DIMS];   // bin-sorted points copy
__device__ float g_nas[MAXPTS];                     // bin-sorted norms
__device__ float g_pk[MAXPTS * SPLITS * 5];
__device__ int   g_pj[MAXPTS * SPLITS * 5];

// ---------------------------------------------------------------------------
// K0: zero the 200MB output with wide stores (measured ~28.5us @ ~4.9TB/s).
// ---------------------------------------------------------------------------
__global__ void __launch_bounds__(256)
zero_kernel(float4* __restrict__ out, size_t n4)
{
    size_t stride = (size_t)gridDim.x * 256;
    float4 z = make_float4(0.f, 0.f, 0.f, 0.f);
    for (size_t i = (size_t)blockIdx.x * 256 + threadIdx.x; i < n4; i += stride)
        out[i] = z;
}

// ---------------------------------------------------------------------------
// K1: LSH projection -> bin id (first-max argmax) + squared norm.
// ---------------------------------------------------------------------------
__global__ void proj_kernel(const float* __restrict__ pts,
                            const float* __restrict__ rot,
                            int total, int nbins, int rotcols)
{
    const int nproj = nbins >> 1;                 // <= 8
    __shared__ float s_rot[8 * DIMS];
    for (int i = threadIdx.x; i < nproj * DIMS; i += blockDim.x) {
        int h = i >> 7, d = i & 127;
        s_rot[h * DIMS + d] = rot[d * rotcols + h];
    }
    __syncthreads();

    int p       = blockIdx.x * 64 + (threadIdx.x >> 2);
    int quarter = threadIdx.x & 3;

    float m[8];
    #pragma unroll
    for (int h = 0; h < 8; h++) m[h] = 0.f;
    float nrm = 0.f;

    if (p < total) {
        const float4* pv = (const float4*)(pts + (size_t)p * DIMS) + quarter * 8;
        #pragma unroll 8
        for (int d4 = 0; d4 < 8; d4++) {
            float4 v = pv[d4];
            nrm += v.x * v.x + v.y * v.y + v.z * v.z + v.w * v.w;
            int d0 = quarter * 32 + d4 * 4;
            for (int h = 0; h < nproj; h++) {
                const float* r = &s_rot[h * DIMS + d0];
                m[h] += v.x * r[0] + v.y * r[1] + v.z * r[2] + v.w * r[3];
            }
        }
    }
    for (int h = 0; h < nproj; h++) {
        m[h] += __shfl_xor_sync(0xffffffffu, m[h], 1);
        m[h] += __shfl_xor_sync(0xffffffffu, m[h], 2);
    }
    nrm += __shfl_xor_sync(0xffffffffu, nrm, 1);
    nrm += __shfl_xor_sync(0xffffffffu, nrm, 2);

    if (quarter == 0 && p < total) {
        float best = m[0]; int bi = 0;
        for (int j = 1; j < nbins; j++) {
            float v = (j < nproj) ? m[j] : -m[j - nproj];
            if (v > best) { best = v; bi = j; }
        }
        g_binid[p] = bi;
        g_na[p]    = nrm;
    }
}

// ---------------------------------------------------------------------------
// K2: stable counting sort of bin ids per batch == jnp.argsort (stable)
// ---------------------------------------------------------------------------
__global__ void sort_kernel(int N, int nbins)
{
    const int T = 256;
    int b   = blockIdx.x;
    int tid = threadIdx.x;
    __shared__ int s_cnt[32 * T];
    __shared__ int s_aux[9];

    int chunk = (N + T - 1) / T;
    int lo = tid * chunk; if (lo > N) lo = N;
    int hi = lo + chunk;  if (hi > N) hi = N;

    for (int bin = 0; bin < nbins; bin++) s_cnt[bin * T + tid] = 0;
    __syncthreads();
    for (int n = lo; n < hi; n++) s_cnt[g_binid[b * N + n] * T + tid]++;
    __syncthreads();

    int run = 0;
    int lane = tid & 31, warp = tid >> 5;
    for (int bin = 0; bin < nbins; bin++) {
        int c = s_cnt[bin * T + tid];
        int x = c;
        #pragma unroll
        for (int o = 1; o < 32; o <<= 1) {
            int y = __shfl_up_sync(0xffffffffu, x, o);
            if (lane >= o) x += y;
        }
        if (lane == 31) s_aux[warp] = x;
        __syncthreads();
        if (warp == 0) {
            int w = (lane < 8) ? s_aux[lane] : 0;
            #pragma unroll
            for (int o = 1; o < 8; o <<= 1) {
                int y = __shfl_up_sync(0xffffffffu, w, o);
                if (lane >= o) w += y;
            }
            if (lane < 8) s_aux[lane] = w;
        }
        __syncthreads();
        int base = (warp > 0) ? s_aux[warp - 1] : 0;
        int ex   = base + x - c;
        int tot  = s_aux[7];
        __syncthreads();
        s_cnt[bin * T + tid] = run + ex;
        run += tot;
        __syncthreads();
    }
    for (int n = lo; n < hi; n++) {
        int bin = g_binid[b * N + n];
        int pos = s_cnt[bin * T + tid]++;
        g_split[b * N + pos] = n;
    }
}

// ---------------------------------------------------------------------------
// K2b: gather points + norms into bin-sorted contiguous order (coalesced).
// ---------------------------------------------------------------------------
__global__ void __launch_bounds__(256)
gather_kernel(const float* __restrict__ pts, int N, int P)
{
    long t = (long)blockIdx.x * 256 + threadIdx.x;   // over P*32 float4s
    int row = (int)(t >> 5);
    int f4  = (int)(t & 31);
    if (row < P) {
        int b = row / N;
        int g = g_split[row];
        float4 v = ((const float4*)(pts + ((size_t)b * N + g) * DIMS))[f4];
        ((float4*)(g_sorted + (size_t)row * DIMS))[f4] = v;
        if (f4 == 0) g_nas[row] = g_na[b * N + g];
    }
}

// ---------------------------------------------------------------------------
// K3: per-(rowtile, colsplit) gram + bottom-5-of-d2 -> partial lists.
// grid = (8 rowtiles * 2 splits, nbins, B); block = 256 = 8(tx) x 32(ty).
// Thread tile 2 rows x 8 cols (halves persistent selection registers vs 4x4).
// __launch_bounds__(256,3) pins occupancy at 3 blocks/SM.
// smem: na@0 (2KB) | rows@2048 (32KB) | cols@34816 (32KB); total 67584.
// merge overlay (post-compute): mk@2048 (10KB), mj@14336 (10KB).
// ---------------------------------------------------------------------------
__global__ void __launch_bounds__(256, 3)
bin_kernel(int N, int nbins)
{
    extern __shared__ char sm[];
    float* s_na   = (float*)sm;
    float* s_rows = (float*)(sm + 2048);
    float* s_cols = (float*)(sm + 34816);
    float* s_mk   = (float*)(sm + 2048);
    int*   s_mj   = (int*)(sm + 14336);

    int bx    = blockIdx.x;
    int tile  = bx >> 1;
    int split = bx & 1;
    int bin   = blockIdx.y;
    int b     = blockIdx.z;
    int tid   = threadIdx.x;
    int tx = tid & 7, ty = tid >> 3;           // tx: 8 cols each, ty: 2 rows each

    const long binbase = (long)b * N + (long)bin * BINSZ;

    for (int i = tid; i < BINSZ; i += 256)
        s_na[i] = g_nas[binbase + i];
    __syncthreads();

    // row tile: coalesced stream, 8 fixed iterations, transposed store
    int row0 = tile * TILE_R;
    #pragma unroll
    for (int it = 0; it < 8; it++) {
        int i  = tid + it * 256;               // 0..2047
        int r  = i & 63, d4 = i >> 6;
        float4 v = make_float4(0.f, 0.f, 0.f, 0.f);
        if (row0 + r < BINSZ)
            v = ((const float4*)(g_sorted + (binbase + row0 + r) * DIMS))[d4];
        s_rows[(d4 * 4 + 0) * TILE_R + r] = v.x;
        s_rows[(d4 * 4 + 1) * TILE_R + r] = v.y;
        s_rows[(d4 * 4 + 2) * TILE_R + r] = v.z;
        s_rows[(d4 * 4 + 3) * TILE_R + r] = v.w;
    }

    float na_row[2];
    float tk[2][5]; int tj[2][5];
    #pragma unroll
    for (int a = 0; a < 2; a++) {
        int grow = row0 + ty * 2 + a;
        na_row[a] = (grow < BINSZ) ? s_na[grow] : 0.f;
        #pragma unroll
        for (int q = 0; q < 5; q++) { tk[a][q] = 3.0e38f; tj[a][q] = 0x7fffffff; }
    }

    const int cbase = split * CPS;
    for (int c = 0; c < (CPS + TILE_C - 1) / TILE_C; c++) {
        __syncthreads();
        int jb = c * TILE_C;
        #pragma unroll
        for (int it = 0; it < 8; it++) {
            int i  = tid + it * 256;
            int j  = i & 63, d4 = i >> 6;
            int jl = jb + j;
            float4 v = make_float4(0.f, 0.f, 0.f, 0.f);
            if (jl < CPS)
                v = ((const float4*)(g_sorted + (binbase + cbase + jl) * DIMS))[d4];
            s_cols[(d4 * 4 + 0) * TILE_C + j] = v.x;
            s_cols[(d4 * 4 + 1) * TILE_C + j] = v.y;
            s_cols[(d4 * 4 + 2) * TILE_C + j] = v.z;
            s_cols[(d4 * 4 + 3) * TILE_C + j] = v.w;
        }
        __syncthreads();

        float acc[2][8];
        #pragma unroll
        for (int a = 0; a < 2; a++)
            #pragma unroll
            for (int q = 0; q < 8; q++) acc[a][q] = 0.f;

        #pragma unroll 4
        for (int d = 0; d < DIMS; d++) {
            float2 rv  = *(const float2*)&s_rows[d * TILE_R + ty * 2];
            float4 cv0 = *(const float4*)&s_cols[d * TILE_C + tx * 8];
            float4 cv1 = *(const float4*)&s_cols[d * TILE_C + tx * 8 + 4];
            acc[0][0] += rv.x * cv0.x; acc[0][1] += rv.x * cv0.y;
            acc[0][2] += rv.x * cv0.z; acc[0][3] += rv.x * cv0.w;
            acc[0][4] += rv.x * cv1.x; acc[0][5] += rv.x * cv1.y;
            acc[0][6] += rv.x * cv1.z; acc[0][7] += rv.x * cv1.w;
            acc[1][0] += rv.y * cv0.x; acc[1][1] += rv.y * cv0.y;
            acc[1][2] += rv.y * cv0.z; acc[1][3] += rv.y * cv0.w;
            acc[1][4] += rv.y * cv1.x; acc[1][5] += rv.y * cv1.y;
            acc[1][6] += rv.y * cv1.z; acc[1][7] += rv.y * cv1.w;
        }

        // candidates: local j ascending per thread -> strict '<' keeps lowest idx
        #pragma unroll
        for (int q = 0; q < 8; q++) {
            int jl = jb + tx * 8 + q;
            if (jl < CPS) {
                float ncol = s_na[cbase + jl];
                #pragma unroll
                for (int a = 0; a < 2; a++) {
                    float key = fmaxf(na_row[a] - 2.f * acc[a][q] + ncol, 1e-6f);
                    if (key < tk[a][4]) {
                        tk[a][4] = key; tj[a][4] = jl;
                        #pragma unroll
                        for (int p = 4; p > 0; p--) {
                            if (tk[a][p] < tk[a][p - 1]) {
                                float kt = tk[a][p]; tk[a][p] = tk[a][p-1]; tk[a][p-1] = kt;
                                int   jt = tj[a][p]; tj[a][p] = tj[a][p-1]; tj[a][p-1] = jt;
                            }
                        }
                    }
                }
            }
        }
    }

    __syncthreads();   // compute done; overlay merge buffers
    #pragma unroll
    for (int a = 0; a < 2; a++) {
        int r = ty * 2 + a;
        int base = (r * 8 + tx) * 5;
        #pragma unroll
        for (int q = 0; q < 5; q++) { s_mk[base + q] = tk[a][q]; s_mj[base + q] = tj[a][q]; }
    }
    __syncthreads();

    if (tid < TILE_R) {
        int r = tid;
        int grow = row0 + r;
        if (grow < BINSZ) {
            float fk[5]; int fj[5];
            #pragma unroll
            for (int q = 0; q < 5; q++) { fk[q] = 3.0e38f; fj[q] = 0x7fffffff; }
            for (int t = 0; t < 8; t++) {
                int base = (r * 8 + t) * 5;
                #pragma unroll
                for (int q = 0; q < 5; q++) {
                    float key = s_mk[base + q]; int j = s_mj[base + q];
                    bool better = (key < fk[4]) || (key == fk[4] && j < fj[4]);
                    if (better) {
                        fk[4] = key; fj[4] = j;
                        #pragma unroll
                        for (int p = 4; p > 0; p--) {
                            bool sw = (fk[p] < fk[p-1]) ||
                                      (fk[p] == fk[p-1] && fj[p] < fj[p-1]);
                            if (sw) {
                                float kt = fk[p]; fk[p] = fk[p-1]; fk[p-1] = kt;
                                int   jt = fj[p]; fj[p] = fj[p-1]; fj[p-1] = jt;
                            }
                        }
                    }
                }
            }
            long base = (((long)(b * nbins + bin) * BINSZ + grow) * SPLITS + split) * 5;
            #pragma unroll
            for (int q = 0; q < 5; q++) {
                g_pk[base + q] = fk[q];
                g_pj[base + q] = cbase + fj[q];
            }
        }
    }
}

// ---------------------------------------------------------------------------
// K4: merge split pairs per row ((key, j) order), eval exp(-0.1*sqrt(d2))
// on the 5 survivors, scatter into dense out.
// ---------------------------------------------------------------------------
__global__ void merge_kernel(float* __restrict__ out, int N, int nbins, int totalRows)
{
    int idx = blockIdx.x * 256 + threadIdx.x;
    if (idx >= totalRows) return;
    int b   = idx / N;
    int rem = idx - b * N;
    int bin = rem / BINSZ;
    int r   = rem - bin * BINSZ;

    long base = (((long)(b * nbins + bin) * BINSZ + r) * SPLITS) * 5;
    const float* ka = &g_pk[base];      const int* ja = &g_pj[base];
    const float* kb = &g_pk[base + 5];  const int* jb = &g_pj[base + 5];

    int src = g_split[b * N + bin * BINSZ + r];
    size_t rowbase = ((size_t)b * N + src) * (size_t)N;

    int pa = 0, pb = 0;
    #pragma unroll
    for (int q = 0; q < 5; q++) {
        bool takeA = (pb >= 5) ||
                     (pa < 5 && (ka[pa] < kb[pb] ||
                                 (ka[pa] == kb[pb] && ja[pa] < jb[pb])));
        float k; int j;
        if (takeA) { k = ka[pa]; j = ja[pa]; pa++; }
        else       { k = kb[pb]; j = jb[pb]; pb++; }
        int dst = g_split[b * N + bin * BINSZ + j];
        out[rowbase + (size_t)dst] = expf(-0.1f * sqrtf(k));
    }
}

// ---------------------------------------------------------------------------
extern "C" void kernel_launch(void* const* d_in, const int* in_sizes, int n_in,
                              void* d_out, int out_size)
{
    const float* pts = (const float*)d_in[0];
    const float* rot = (const float*)d_in[1];

    int P       = in_sizes[0] / DIMS;              // B*N
    int rotcols = in_sizes[1] / DIMS;              // MAX_NUM_BINS/2
    int N       = (int)((long long)out_size / P);  // out = B*N*N
    int nbins   = N / BINSZ;
    int B       = P / N;

    cudaStream_t s2;
    cudaEvent_t  e1, e2;
    cudaStreamCreateWithFlags(&s2, cudaStreamNonBlocking);
    cudaEventCreateWithFlags(&e1, cudaEventDisableTiming);
    cudaEventCreateWithFlags(&e2, cudaEventDisableTiming);

    cudaEventRecord(e1, 0);
    cudaStreamWaitEvent(s2, e1, 0);

    int gatherBlocks = (int)(((long)P * 32 + 255) / 256);

    proj_kernel<<<(P + 63) / 64, 256, 0, s2>>>(pts, rot, P, nbins, rotcols);   // 1
    sort_kernel<<<B, 256, 0, s2>>>(N, nbins);                                  // 2
    gather_kernel<<<gatherBlocks, 256, 0, s2>>>(pts, N, P);                    // 3

    size_t n4 = ((size_t)P * (size_t)N) / 4;
    zero_kernel<<<4096, 256>>>((float4*)d_out, n4);                            // 4 (main)

    gather_kernel<<<gatherBlocks, 256, 0, s2>>>(pts, N, P);                    // 5 (idempotent)

    const int smem_bytes = 67584;
    cudaFuncSetAttribute(bin_kernel, cudaFuncAttributeMaxDynamicSharedMemorySize, smem_bytes);
    dim3 grid(((BINSZ + TILE_R - 1) / TILE_R) * SPLITS, nbins, B);
    bin_kernel<<<grid, 256, smem_bytes, s2>>>(N, nbins);                       // 6
    cudaEventRecord(e2, s2);

    cudaStreamWaitEvent(0, e2, 0);
    merge_kernel<<<(P + 255) / 256, 256>>>((float*)d_out, N, nbins, P);        // 7
}

// round 14
// speedup vs baseline: 1.4294x; 1.4294x over previous
#include <cuda_runtime.h>
#include <cstdint>
#include <math.h>

#define DIMS   128
#define BINSZ  500
#define TILE_R 64
#define TILE_C 64
#define SPLITS 2
#define CPS    250      // cols per split
#define MAXPTS 65536

// scratch (allocation-free rule: __device__ globals)
__device__ int   g_binid[MAXPTS];
__device__ float g_na[MAXPTS];
__device__ int   g_split[MAXPTS];
__device__ float g_sorted[(size_t)MAXPTS * DIMS];   // bin-sorted points copy
__device__ float g_nas[MAXPTS];                     // bin-sorted norms
__device__ float g_pk[MAXPTS * SPLITS * 5];
__device__ int   g_pj[MAXPTS * SPLITS * 5];

// ---------------------------------------------------------------------------
// K0: zero the 200MB output with wide stores (measured ~28.5us @ ~4.9TB/s).
// ---------------------------------------------------------------------------
__global__ void __launch_bounds__(256)
zero_kernel(float4* __restrict__ out, size_t n4)
{
    size_t stride = (size_t)gridDim.x * 256;
    float4 z = make_float4(0.f, 0.f, 0.f, 0.f);
    for (size_t i = (size_t)blockIdx.x * 256 + threadIdx.x; i < n4; i += stride)
        out[i] = z;
}

// ---------------------------------------------------------------------------
// K1: LSH projection -> bin id (first-max argmax) + squared norm.
// ---------------------------------------------------------------------------
__global__ void proj_kernel(const float* __restrict__ pts,
                            const float* __restrict__ rot,
                            int total, int nbins, int rotcols)
{
    const int nproj = nbins >> 1;                 // <= 8
    __shared__ float s_rot[8 * DIMS];
    for (int i = threadIdx.x; i < nproj * DIMS; i += blockDim.x) {
        int h = i >> 7, d = i & 127;
        s_rot[h * DIMS + d] = rot[d * rotcols + h];
    }
    __syncthreads();

    int p       = blockIdx.x * 64 + (threadIdx.x >> 2);
    int quarter = threadIdx.x & 3;

    float m[8];
    #pragma unroll
    for (int h = 0; h < 8; h++) m[h] = 0.f;
    float nrm = 0.f;

    if (p < total) {
        const float4* pv = (const float4*)(pts + (size_t)p * DIMS) + quarter * 8;
        #pragma unroll 8
        for (int d4 = 0; d4 < 8; d4++) {
            float4 v = pv[d4];
            nrm += v.x * v.x + v.y * v.y + v.z * v.z + v.w * v.w;
            int d0 = quarter * 32 + d4 * 4;
            for (int h = 0; h < nproj; h++) {
                const float* r = &s_rot[h * DIMS + d0];
                m[h] += v.x * r[0] + v.y * r[1] + v.z * r[2] + v.w * r[3];
            }
        }
    }
    for (int h = 0; h < nproj; h++) {
        m[h] += __shfl_xor_sync(0xffffffffu, m[h], 1);
        m[h] += __shfl_xor_sync(0xffffffffu, m[h], 2);
    }
    nrm += __shfl_xor_sync(0xffffffffu, nrm, 1);
    nrm += __shfl_xor_sync(0xffffffffu, nrm, 2);

    if (quarter == 0 && p < total) {
        float best = m[0]; int bi = 0;
        for (int j = 1; j < nbins; j++) {
            float v = (j < nproj) ? m[j] : -m[j - nproj];
            if (v > best) { best = v; bi = j; }
        }
        g_binid[p] = bi;
        g_na[p]    = nrm;
    }
}

// ---------------------------------------------------------------------------
// K2: stable counting sort of bin ids per batch == jnp.argsort (stable)
// ---------------------------------------------------------------------------
__global__ void sort_kernel(int N, int nbins)
{
    const int T = 256;
    int b   = blockIdx.x;
    int tid = threadIdx.x;
    __shared__ int s_cnt[32 * T];
    __shared__ int s_aux[9];

    int chunk = (N + T - 1) / T;
    int lo = tid * chunk; if (lo > N) lo = N;
    int hi = lo + chunk;  if (hi > N) hi = N;

    for (int bin = 0; bin < nbins; bin++) s_cnt[bin * T + tid] = 0;
    __syncthreads();
    for (int n = lo; n < hi; n++) s_cnt[g_binid[b * N + n] * T + tid]++;
    __syncthreads();

    int run = 0;
    int lane = tid & 31, warp = tid >> 5;
    for (int bin = 0; bin < nbins; bin++) {
        int c = s_cnt[bin * T + tid];
        int x = c;
        #pragma unroll
        for (int o = 1; o < 32; o <<= 1) {
            int y = __shfl_up_sync(0xffffffffu, x, o);
            if (lane >= o) x += y;
        }
        if (lane == 31) s_aux[warp] = x;
        __syncthreads();
        if (warp == 0) {
            int w = (lane < 8) ? s_aux[lane] : 0;
            #pragma unroll
            for (int o = 1; o < 8; o <<= 1) {
                int y = __shfl_up_sync(0xffffffffu, w, o);
                if (lane >= o) w += y;
            }
            if (lane < 8) s_aux[lane] = w;
        }
        __syncthreads();
        int base = (warp > 0) ? s_aux[warp - 1] : 0;
        int ex   = base + x - c;
        int tot  = s_aux[7];
        __syncthreads();
        s_cnt[bin * T + tid] = run + ex;
        run += tot;
        __syncthreads();
    }
    for (int n = lo; n < hi; n++) {
        int bin = g_binid[b * N + n];
        int pos = s_cnt[bin * T + tid]++;
        g_split[b * N + pos] = n;
    }
}

// ---------------------------------------------------------------------------
// K2b: gather points + norms into bin-sorted contiguous order (coalesced).
// ---------------------------------------------------------------------------
__global__ void __launch_bounds__(256)
gather_kernel(const float* __restrict__ pts, int N, int P)
{
    long t = (long)blockIdx.x * 256 + threadIdx.x;   // over P*32 float4s
    int row = (int)(t >> 5);
    int f4  = (int)(t & 31);
    if (row < P) {
        int b = row / N;
        int g = g_split[row];
        float4 v = ((const float4*)(pts + ((size_t)b * N + g) * DIMS))[f4];
        ((float4*)(g_sorted + (size_t)row * DIMS))[f4] = v;
        if (f4 == 0) g_nas[row] = g_na[b * N + g];
    }
}

// ---------------------------------------------------------------------------
// K3: per-(rowtile, colsplit) gram + bottom-5-of-d2 -> partial lists.
// grid = (8 rowtiles * 2 splits, nbins, B); block = 256 = 16(tx) x 16(ty).
// Thread tile 4x4. All global loads COALESCED from g_sorted, fully unrolled.
// (Exact R11 code — best measured config.)
// smem: na@0 (2KB) | rows@2048 (32KB) | cols@34816 (32KB); total 67584.
// merge overlay (post-compute): mk@2048 (20KB), mj@24576 (20KB).
// ---------------------------------------------------------------------------
__global__ void __launch_bounds__(256)
bin_kernel(int N, int nbins)
{
    extern __shared__ char sm[];
    float* s_na   = (float*)sm;
    float* s_rows = (float*)(sm + 2048);
    float* s_cols = (float*)(sm + 34816);
    float* s_mk   = (float*)(sm + 2048);
    int*   s_mj   = (int*)(sm + 24576);

    int bx    = blockIdx.x;
    int tile  = bx >> 1;
    int split = bx & 1;
    int bin   = blockIdx.y;
    int b     = blockIdx.z;
    int tid   = threadIdx.x;
    int tx = tid & 15, ty = tid >> 4;          // 4 cols, 4 rows per thread

    const long binbase = (long)b * N + (long)bin * BINSZ;   // row offset in g_sorted

    for (int i = tid; i < BINSZ; i += 256)
        s_na[i] = g_nas[binbase + i];
    __syncthreads();

    // row tile: coalesced stream, 8 fixed iterations, transposed store
    int row0 = tile * TILE_R;
    #pragma unroll
    for (int it = 0; it < 8; it++) {
        int i  = tid + it * 256;               // 0..2047
        int r  = i & 63, d4 = i >> 6;
        float4 v = make_float4(0.f, 0.f, 0.f, 0.f);
        if (row0 + r < BINSZ)
            v = ((const float4*)(g_sorted + (binbase + row0 + r) * DIMS))[d4];
        s_rows[(d4 * 4 + 0) * TILE_R + r] = v.x;
        s_rows[(d4 * 4 + 1) * TILE_R + r] = v.y;
        s_rows[(d4 * 4 + 2) * TILE_R + r] = v.z;
        s_rows[(d4 * 4 + 3) * TILE_R + r] = v.w;
    }

    float na_row[4];
    float tk[4][5]; int tj[4][5];
    #pragma unroll
    for (int a = 0; a < 4; a++) {
        int grow = row0 + ty * 4 + a;
        na_row[a] = (grow < BINSZ) ? s_na[grow] : 0.f;
        #pragma unroll
        for (int q = 0; q < 5; q++) { tk[a][q] = 3.0e38f; tj[a][q] = 0x7fffffff; }
    }

    const int cbase = split * CPS;
    for (int c = 0; c < (CPS + TILE_C - 1) / TILE_C; c++) {
        __syncthreads();
        int jb = c * TILE_C;
        #pragma unroll
        for (int it = 0; it < 8; it++) {
            int i  = tid + it * 256;
            int j  = i & 63, d4 = i >> 6;
            int jl = jb + j;
            float4 v = make_float4(0.f, 0.f, 0.f, 0.f);
            if (jl < CPS)
                v = ((const float4*)(g_sorted + (binbase + cbase + jl) * DIMS))[d4];
            s_cols[(d4 * 4 + 0) * TILE_C + j] = v.x;
            s_cols[(d4 * 4 + 1) * TILE_C + j] = v.y;
            s_cols[(d4 * 4 + 2) * TILE_C + j] = v.z;
            s_cols[(d4 * 4 + 3) * TILE_C + j] = v.w;
        }
        __syncthreads();

        float acc[4][4];
        #pragma unroll
        for (int a = 0; a < 4; a++)
            #pragma unroll
            for (int q = 0; q < 4; q++) acc[a][q] = 0.f;

        #pragma unroll 4
        for (int d = 0; d < DIMS; d++) {
            float4 rv = *(const float4*)&s_rows[d * TILE_R + ty * 4];
            float4 cv = *(const float4*)&s_cols[d * TILE_C + tx * 4];
            acc[0][0] += rv.x * cv.x; acc[0][1] += rv.x * cv.y;
            acc[0][2] += rv.x * cv.z; acc[0][3] += rv.x * cv.w;
            acc[1][0] += rv.y * cv.x; acc[1][1] += rv.y * cv.y;
            acc[1][2] += rv.y * cv.z; acc[1][3] += rv.y * cv.w;
            acc[2][0] += rv.z * cv.x; acc[2][1] += rv.z * cv.y;
            acc[2][2] += rv.z * cv.z; acc[2][3] += rv.z * cv.w;
            acc[3][0] += rv.w * cv.x; acc[3][1] += rv.w * cv.y;
            acc[3][2] += rv.w * cv.z; acc[3][3] += rv.w * cv.w;
        }

        // candidates: local j ascending per thread -> strict '<' keeps lowest idx
        #pragma unroll
        for (int q = 0; q < 4; q++) {
            int jl = jb + tx * 4 + q;
            if (jl < CPS) {
                float ncol = s_na[cbase + jl];
                #pragma unroll
                for (int a = 0; a < 4; a++) {
                    float key = fmaxf(na_row[a] - 2.f * acc[a][q] + ncol, 1e-6f);
                    if (key < tk[a][4]) {
                        tk[a][4] = key; tj[a][4] = jl;
                        #pragma unroll
                        for (int p = 4; p > 0; p--) {
                            if (tk[a][p] < tk[a][p - 1]) {
                                float kt = tk[a][p]; tk[a][p] = tk[a][p-1]; tk[a][p-1] = kt;
                                int   jt = tj[a][p]; tj[a][p] = tj[a][p-1]; tj[a][p-1] = jt;
                            }
                        }
                    }
                }
            }
        }
    }

    __syncthreads();   // compute done; overlay merge buffers
    #pragma unroll
    for (int a = 0; a < 4; a++) {
        int r = ty * 4 + a;
        int base = (r * 16 + tx) * 5;
        #pragma unroll
        for (int q = 0; q < 5; q++) { s_mk[base + q] = tk[a][q]; s_mj[base + q] = tj[a][q]; }
    }
    __syncthreads();

    if (tid < TILE_R) {
        int r = tid;
        int grow = row0 + r;
        if (grow < BINSZ) {
            float fk[5]; int fj[5];
            #pragma unroll
            for (int q = 0; q < 5; q++) { fk[q] = 3.0e38f; fj[q] = 0x7fffffff; }
            for (int t = 0; t < 16; t++) {
                int base = (r * 16 + t) * 5;
                #pragma unroll
                for (int q = 0; q < 5; q++) {
                    float key = s_mk[base + q]; int j = s_mj[base + q];
                    bool better = (key < fk[4]) || (key == fk[4] && j < fj[4]);
                    if (better) {
                        fk[4] = key; fj[4] = j;
                        #pragma unroll
                        for (int p = 4; p > 0; p--) {
                            bool sw = (fk[p] < fk[p-1]) ||
                                      (fk[p] == fk[p-1] && fj[p] < fj[p-1]);
                            if (sw) {
                                float kt = fk[p]; fk[p] = fk[p-1]; fk[p-1] = kt;
                                int   jt = fj[p]; fj[p] = fj[p-1]; fj[p-1] = jt;
                            }
                        }
                    }
                }
            }
            long base = (((long)(b * nbins + bin) * BINSZ + grow) * SPLITS + split) * 5;
            #pragma unroll
            for (int q = 0; q < 5; q++) {
                g_pk[base + q] = fk[q];
                g_pj[base + q] = cbase + fj[q];   // global index within bin
            }
        }
    }
}

// ---------------------------------------------------------------------------
// K4: merge split pairs per row ((key, j) order), eval exp(-0.1*sqrt(d2))
// on the 5 survivors, scatter into dense out.
// ---------------------------------------------------------------------------
__global__ void merge_kernel(float* __restrict__ out, int N, int nbins, int totalRows)
{
    int idx = blockIdx.x * 256 + threadIdx.x;
    if (idx >= totalRows) return;
    int b   = idx / N;
    int rem = idx - b * N;
    int bin = rem / BINSZ;
    int r   = rem - bin * BINSZ;

    long base = (((long)(b * nbins + bin) * BINSZ + r) * SPLITS) * 5;
    const float* ka = &g_pk[base];      const int* ja = &g_pj[base];
    const float* kb = &g_pk[base + 5];  const int* jb = &g_pj[base + 5];

    int src = g_split[b * N + bin * BINSZ + r];
    size_t rowbase = ((size_t)b * N + src) * (size_t)N;

    int pa = 0, pb = 0;
    #pragma unroll
    for (int q = 0; q < 5; q++) {
        bool takeA = (pb >= 5) ||
                     (pa < 5 && (ka[pa] < kb[pb] ||
                                 (ka[pa] == kb[pb] && ja[pa] < jb[pb])));
        float k; int j;
        if (takeA) { k = ka[pa]; j = ja[pa]; pa++; }
        else       { k = kb[pb]; j = jb[pb]; pb++; }
        int dst = g_split[b * N + bin * BINSZ + j];
        out[rowbase + (size_t)dst] = expf(-0.1f * sqrtf(k));
    }
}

// ---------------------------------------------------------------------------
extern "C" void kernel_launch(void* const* d_in, const int* in_sizes, int n_in,
                              void* d_out, int out_size)
{
    const float* pts = (const float*)d_in[0];
    const float* rot = (const float*)d_in[1];

    int P       = in_sizes[0] / DIMS;              // B*N
    int rotcols = in_sizes[1] / DIMS;              // MAX_NUM_BINS/2
    int N       = (int)((long long)out_size / P);  // out = B*N*N
    int nbins   = N / BINSZ;
    int B       = P / N;

    cudaStream_t s2;
    cudaEvent_t  e1, e2;
    cudaStreamCreateWithFlags(&s2, cudaStreamNonBlocking);
    cudaEventCreateWithFlags(&e1, cudaEventDisableTiming);
    cudaEventCreateWithFlags(&e2, cudaEventDisableTiming);

    cudaEventRecord(e1, 0);
    cudaStreamWaitEvent(s2, e1, 0);

    int gatherBlocks = (int)(((long)P * 32 + 255) / 256);

    // API launch order: bin_kernel is my 4th launch. The harness issues ~2
    // launches before kernel_launch, so ncu -s 5 -c 1 (absolute launch #6)
    // lands on bin_kernel — the kernel we actually need profiled.
    proj_kernel<<<(P + 63) / 64, 256, 0, s2>>>(pts, rot, P, nbins, rotcols);   // 1
    sort_kernel<<<B, 256, 0, s2>>>(N, nbins);                                  // 2
    gather_kernel<<<gatherBlocks, 256, 0, s2>>>(pts, N, P);                    // 3

    const int smem_bytes = 67584;
    cudaFuncSetAttribute(bin_kernel, cudaFuncAttributeMaxDynamicSharedMemorySize, smem_bytes);
    dim3 grid(((BINSZ + TILE_R - 1) / TILE_R) * SPLITS, nbins, B);
    bin_kernel<<<grid, 256, smem_bytes, s2>>>(N, nbins);                       // 4
    cudaEventRecord(e2, s2);

    // output zeroing on the main stream; no deps -> overlaps the whole chain
    size_t n4 = ((size_t)P * (size_t)N) / 4;
    zero_kernel<<<4096, 256>>>((float4*)d_out, n4);                            // 5

    cudaStreamWaitEvent(0, e2, 0);
    merge_kernel<<<(P + 255) / 256, 256>>>((float*)d_out, N, nbins, P);        // 6
}